// round 14
// baseline (speedup 1.0000x reference)
#include <cuda_runtime.h>
#include <cuda_bf16.h>
#include <cstdint>
#include <cstddef>

// CombineGraph: h = emb[inputs]; e_k = leakyrelu(einsum(bid,bjd,d->bij; h,h,a_k));
// alpha = softmax(select_by_adj(e_k, -9e15)); out = alpha @ h.
// B=512, L=100, D=128. One CTA/batch, 448 threads (14 warps), 2 CTA/SM.
// GEMM1: bf16 symmetric triangle, 28 m16n16 tiles = 2 perfect warp-rounds;
// epilogue writes direct+mirror f32 logits straight to al (race-free, no staging).
// Softmax: in-place Dekker split -> bf16 ah|al_lo. GEMM2: split-bf16 ldmatrix,
// 28 jobs = 2 perfect rounds.

#define B_    512
#define L_    100
#define D_    128
#define NT    448        // threads per CTA (14 warps)
#define HB    68         // h bf16 row stride (u32 words): 272B/row, ldmatrix conflict-free
#define AS    108        // al row stride (f32 words); bf16 era: words 0-51 ah, 52-103 al_lo
#define ADJS  104        // adj row stride (bytes)
#define NEG_INF_ -9e15f

// ---- smem byte offsets ----
#define OFF_HBH  0        // h_hi bf16: 104*68*4 = 28288
#define OFF_HBL  28288    // h_lo bf16: -> 56576
#define OFF_ATP  56576    // a packed uint4[64]: -> 57600
#define OFF_ADJ  57600    // adj int8 100*104: -> 68000
#define OFF_AL   68000    // alpha f32 104*108*4 = 44928: -> 112928
#define SMEM_TOTAL 112928

__device__ __forceinline__ uint32_t smem_u32(const void* p) {
    uint32_t a;
    asm("{ .reg .u64 t; cvta.to.shared.u64 t, %1; cvt.u32.u64 %0, t; }" : "=r"(a) : "l"(p));
    return a;
}
__device__ __forceinline__ unsigned pack_bf16x2(float lo, float hi) {
    unsigned r; asm("cvt.rn.satfinite.bf16x2.f32 %0, %1, %2;" : "=r"(r) : "f"(hi), "f"(lo));
    return r;
}
__device__ __forceinline__ unsigned mulbf2(unsigned a, unsigned b) {
    unsigned r; asm("mul.bf16x2 %0, %1, %2;" : "=r"(r) : "r"(a), "r"(b));
    return r;
}
__device__ __forceinline__ void ldsm_x4(unsigned& r0, unsigned& r1, unsigned& r2, unsigned& r3,
                                        uint32_t addr) {
    asm volatile("ldmatrix.sync.aligned.m8n8.x4.shared.b16 {%0,%1,%2,%3}, [%4];"
                 : "=r"(r0), "=r"(r1), "=r"(r2), "=r"(r3) : "r"(addr));
}
__device__ __forceinline__ void ldsm_x4t(unsigned& r0, unsigned& r1, unsigned& r2, unsigned& r3,
                                         uint32_t addr) {
    asm volatile("ldmatrix.sync.aligned.m8n8.x4.trans.shared.b16 {%0,%1,%2,%3}, [%4];"
                 : "=r"(r0), "=r"(r1), "=r"(r2), "=r"(r3) : "r"(addr));
}
__device__ __forceinline__ void ldsm_x2(unsigned& r0, unsigned& r1, uint32_t addr) {
    asm volatile("ldmatrix.sync.aligned.m8n8.x2.shared.b16 {%0,%1}, [%2];"
                 : "=r"(r0), "=r"(r1) : "r"(addr));
}
__device__ __forceinline__ void mma_bf16(float* c, unsigned a0, unsigned a1,
                                         unsigned a2, unsigned a3,
                                         unsigned b0, unsigned b1) {
    asm volatile(
        "mma.sync.aligned.m16n8k16.row.col.f32.bf16.bf16.f32 "
        "{%0,%1,%2,%3},{%4,%5,%6,%7},{%8,%9},{%0,%1,%2,%3};\n"
        : "+f"(c[0]), "+f"(c[1]), "+f"(c[2]), "+f"(c[3])
        : "r"(a0), "r"(a1), "r"(a2), "r"(a3), "r"(b0), "r"(b1));
}

// triangle decode: jobs 0..27 -> (mt, np) with np >= mt (m16 x n16 tiles)
__device__ __forceinline__ void decode_job(int job, int& mt, int& np) {
    mt = (job >= 27) ? 6 : (job >= 25) ? 5 : (job >= 22) ? 4 :
         (job >= 18) ? 3 : (job >= 13) ? 2 : (job >= 7) ? 1 : 0;
    int base = (mt == 6) ? 27 : (mt == 5) ? 25 : (mt == 4) ? 22 :
               (mt == 3) ? 18 : (mt == 2) ? 13 : (mt == 1) ? 7 : 0;
    np = mt + (job - base);
}

// One GEMM1 tile job (mt, np>=mt). Writes direct + mirrored selected logits to al.
__device__ __forceinline__ void gemm1_job(char* smem, int mt, int np,
                                          uint32_t hb_u, int lane, int g, int t4) {
    const char*  adj_sm = smem + OFF_ADJ;
    const uint4* atp4   = (const uint4*)(smem + OFF_ATP);
    float*       al_sm  = (float*)(smem + OFF_AL);
    const int r0 = mt * 16, jc0 = np * 16;

    int ra = r0 + (lane & 15);  if (ra > 103) ra = 103;
    int rb = jc0 + (lane & 15); if (rb > 103) rb = 103;
    uint32_t a_addr = hb_u + (uint32_t)(ra * HB + ((lane >> 4) << 2)) * 4u;
    uint32_t b_addr = hb_u + (uint32_t)(rb * HB + ((lane >> 4) << 2)) * 4u;
    const uint4* pt = atp4 + t4;

    float c[2][4][4];
    #pragma unroll
    for (int nn = 0; nn < 2; ++nn)
        #pragma unroll
        for (int k = 0; k < 4; ++k)
            #pragma unroll
            for (int p = 0; p < 4; ++p) c[nn][k][p] = 0.f;

    #pragma unroll 2
    for (int ks = 0; ks < 8; ++ks) {
        unsigned A0, A1, A2, A3, B0, B1, B2, B3;
        ldsm_x4(A0, A1, A2, A3, a_addr + ks * 32u);
        ldsm_x4(B0, B1, B2, B3, b_addr + ks * 32u);   // nn0:(B0,B2) nn1:(B1,B3)
        uint4 ap0 = pt[ks * 8];
        uint4 ap1 = pt[ks * 8 + 4];
        mma_bf16(c[0][0], A0, A1, A2, A3, mulbf2(B0, ap0.x), mulbf2(B2, ap1.x));
        mma_bf16(c[0][1], A0, A1, A2, A3, mulbf2(B0, ap0.y), mulbf2(B2, ap1.y));
        mma_bf16(c[0][2], A0, A1, A2, A3, mulbf2(B0, ap0.z), mulbf2(B2, ap1.z));
        mma_bf16(c[0][3], A0, A1, A2, A3, mulbf2(B0, ap0.w), mulbf2(B2, ap1.w));
        mma_bf16(c[1][0], A0, A1, A2, A3, mulbf2(B1, ap0.x), mulbf2(B3, ap1.x));
        mma_bf16(c[1][1], A0, A1, A2, A3, mulbf2(B1, ap0.y), mulbf2(B3, ap1.y));
        mma_bf16(c[1][2], A0, A1, A2, A3, mulbf2(B1, ap0.z), mulbf2(B3, ap1.z));
        mma_bf16(c[1][3], A0, A1, A2, A3, mulbf2(B1, ap0.w), mulbf2(B3, ap1.w));
    }

    // epilogue: select by adj (direct) and adj^T (mirror), leaky-relu, write al
    #pragma unroll
    for (int nn = 0; nn < 2; ++nn) {
        int col0 = jc0 + 8 * nn + 2 * t4;
        #pragma unroll
        for (int hf = 0; hf < 2; ++hf) {
            int row = r0 + g + 8 * hf;
            float vD[2], vM[2];
            #pragma unroll
            for (int e = 0; e < 2; ++e) {
                int col = col0 + e;
                int p = 2 * hf + e;
                float xD = NEG_INF_, xM = NEG_INF_;
                if (row < L_ && col < L_) {
                    int t = adj_sm[row * ADJS + col];
                    float x = (t == 1) ? c[nn][0][p] : (t == 2) ? c[nn][1][p] :
                              (t == 3) ? c[nn][2][p] : (t == 4) ? c[nn][3][p] : 0.f;
                    x = (x > 0.f) ? x : 0.2f * x;
                    xD = t ? x : NEG_INF_;
                    int tm = adj_sm[col * ADJS + row];
                    float y = (tm == 1) ? c[nn][0][p] : (tm == 2) ? c[nn][1][p] :
                              (tm == 3) ? c[nn][2][p] : (tm == 4) ? c[nn][3][p] : 0.f;
                    y = (y > 0.f) ? y : 0.2f * y;
                    xM = tm ? y : NEG_INF_;
                }
                vD[e] = xD; vM[e] = xM;
            }
            if (row < 104 && col0 < 104)   // direct (upper-triangle tile cell)
                *(float2*)(al_sm + row * AS + col0) = make_float2(vD[0], vD[1]);
            if (np > mt && row < L_) {     // mirror into strictly-lower tiles
                if (col0 < L_)     al_sm[col0 * AS + row]       = vM[0];
                if (col0 + 1 < L_) al_sm[(col0 + 1) * AS + row] = vM[1];
            }
        }
    }
}

__global__ __launch_bounds__(NT, 2)
void combine_graph_kernel(const int* __restrict__ inputs,
                          const int* __restrict__ adj,
                          const float* __restrict__ emb,
                          const float* __restrict__ a0p,
                          const float* __restrict__ a1p,
                          const float* __restrict__ a2p,
                          const float* __restrict__ a3p,
                          float* __restrict__ out)
{
    extern __shared__ char smem[];
    unsigned* hbh_sm = (unsigned*)(smem + OFF_HBH);
    unsigned* hbl_sm = (unsigned*)(smem + OFF_HBL);
    unsigned* atp_sm = (unsigned*)(smem + OFF_ATP);
    char*     adj_sm = smem + OFF_ADJ;
    float*    al_sm  = (float*)(smem + OFF_AL);
    unsigned* al32   = (unsigned*)(smem + OFF_AL);
    const uint32_t hbh_u = smem_u32(smem + OFF_HBH);
    const uint32_t hbl_u = smem_u32(smem + OFF_HBL);
    const uint32_t al_u  = smem_u32(smem + OFF_AL);

    const int b    = blockIdx.x;
    const int tid  = threadIdx.x;
    const int w    = tid >> 5;
    const int lane = tid & 31;
    const int g    = lane >> 2;
    const int t4   = lane & 3;

    const int* inp  = inputs + b * L_;
    const int* adjb = adj + (size_t)b * (L_ * L_);

    // ---------------- phase 0: loads ----------------
    if (tid < 256) {   // atp[wd] = {pack(a0),pack(a1),pack(a2),pack(a3)} for word wd
        int wd = tid & 63, k = tid >> 6;
        const float* ap = (k == 0) ? a0p : (k == 1) ? a1p : (k == 2) ? a2p : a3p;
        ((unsigned*)((uint4*)atp_sm + wd))[k] = pack_bf16x2(ap[2 * wd], ap[2 * wd + 1]);
    }
    // embedding gather -> hb_hi + hb_lo (Dekker split); rows 100..103 zero
    for (int e = tid; e < 104 * 32; e += NT) {
        int r = e >> 5, q = e & 31;
        float4 v = make_float4(0.f, 0.f, 0.f, 0.f);
        if (r < L_) {
            int id = inp[r];
            v = ((const float4*)(emb + (size_t)id * D_))[q];
        }
        unsigned hi0 = pack_bf16x2(v.x, v.y);
        unsigned hi1 = pack_bf16x2(v.z, v.w);
        float rx = v.x - __uint_as_float(hi0 << 16);
        float ry = v.y - __uint_as_float(hi0 & 0xffff0000u);
        float rz = v.z - __uint_as_float(hi1 << 16);
        float rw = v.w - __uint_as_float(hi1 & 0xffff0000u);
        *(uint2*)(hbh_sm + r * HB + 2 * q) = make_uint2(hi0, hi1);
        *(uint2*)(hbl_sm + r * HB + 2 * q) = make_uint2(pack_bf16x2(rx, ry),
                                                        pack_bf16x2(rz, rw));
    }
    // adj -> int8
    for (int e = tid; e < 2500; e += NT) {
        int i = e / 25, c = e % 25;
        int4 v = ((const int4*)(adjb + i * 100))[c];
        unsigned p = (unsigned)(v.x & 0xff) | ((unsigned)(v.y & 0xff) << 8)
                   | ((unsigned)(v.z & 0xff) << 16) | ((unsigned)(v.w & 0xff) << 24);
        *(unsigned*)(adj_sm + i * ADJS + c * 4) = p;
    }
    __syncthreads();

    // ---- GEMM1: 28 upper-triangle m16n16 tiles = 2 perfect rounds on 14 warps ----
    {
        int mt, np;
        decode_job(w, mt, np);
        gemm1_job(smem, mt, np, hbh_u, lane, g, t4);
        decode_job(w + 14, mt, np);
        gemm1_job(smem, mt, np, hbh_u, lane, g, t4);
    }
    __syncthreads();

    // -------- softmax + in-place Dekker split: al f32 row -> ah | al_lo bf16 --------
    for (int i = w; i < L_; i += 14) {
        float4 x = make_float4(NEG_INF_, NEG_INF_, NEG_INF_, NEG_INF_);
        if (lane < 26) x = *(const float4*)(al_sm + i * AS + 4 * lane);
        float mx = fmaxf(fmaxf(x.x, x.y), fmaxf(x.z, x.w));
        #pragma unroll
        for (int o = 16; o > 0; o >>= 1) mx = fmaxf(mx, __shfl_xor_sync(0xffffffffu, mx, o));
        float4 ev = make_float4(0.f, 0.f, 0.f, 0.f);
        if (lane < 25) {   // cols 100..103 masked out
            ev.x = __expf(x.x - mx); ev.y = __expf(x.y - mx);
            ev.z = __expf(x.z - mx); ev.w = __expf(x.w - mx);
        }
        float s = (ev.x + ev.y) + (ev.z + ev.w);
        #pragma unroll
        for (int o = 16; o > 0; o >>= 1) s += __shfl_xor_sync(0xffffffffu, s, o);
        float inv = 1.f / s;
        if (lane < 26) {   // warp-synchronous: all reads done before these writes
            float a0 = ev.x * inv, a1 = ev.y * inv, a2 = ev.z * inv, a3 = ev.w * inv;
            unsigned h0 = pack_bf16x2(a0, a1);
            unsigned h1 = pack_bf16x2(a2, a3);
            float l0 = a0 - __uint_as_float(h0 << 16);
            float l1 = a1 - __uint_as_float(h0 & 0xffff0000u);
            float l2 = a2 - __uint_as_float(h1 << 16);
            float l3 = a3 - __uint_as_float(h1 & 0xffff0000u);
            *(uint2*)(al32 + i * AS + 2 * lane)      = make_uint2(h0, h1);
            *(uint2*)(al32 + i * AS + 52 + 2 * lane) = make_uint2(pack_bf16x2(l0, l1),
                                                                  pack_bf16x2(l2, l3));
        }
    }
    __syncthreads();

    // ------- GEMM2: out = ah @ (hh + hl) + al @ hh  (bf16 split, ldmatrix) -------
    #pragma unroll
    for (int kk = 0; kk < 2; ++kk) {
        int job = w + 14 * kk;    // 28 jobs = 2 perfect rounds
        {
            int mt16 = job >> 2;          // 0..6
            int nq   = job & 3;           // n32 quarter of D
            const int r0 = mt16 * 16;

            int rowA = r0 + (lane & 15); if (rowA > 103) rowA = 103;
            uint32_t ahA  = al_u + (uint32_t)(rowA * (AS * 4)) + (uint32_t)((lane >> 4) << 4);
            uint32_t alA  = ahA + 208u;
            uint32_t ahA6 = al_u + (uint32_t)(rowA * (AS * 4)) + 192u;
            uint32_t alA6 = ahA6 + 208u;
            const uint32_t bcol = (uint32_t)(nq * 64) + (uint32_t)((lane >> 4) << 4);

            float c[4][4];
            #pragma unroll
            for (int n = 0; n < 4; ++n)
                #pragma unroll
                for (int p = 0; p < 4; ++p) c[n][p] = 0.f;

            #pragma unroll 1
            for (int kt = 0; kt < 7; ++kt) {
                int jr = kt * 16 + (lane & 15); if (jr > 103) jr = 103;
                uint32_t boff = (uint32_t)(jr * (HB * 4)) + bcol;
                unsigned hh[8], hl[8];
                ldsm_x4t(hh[0], hh[1], hh[2], hh[3], hbh_u + boff);
                ldsm_x4t(hh[4], hh[5], hh[6], hh[7], hbh_u + boff + 32u);
                ldsm_x4t(hl[0], hl[1], hl[2], hl[3], hbl_u + boff);
                ldsm_x4t(hl[4], hl[5], hl[6], hl[7], hbl_u + boff + 32u);
                unsigned Ah[4], Al[4];
                if (kt < 6) {
                    ldsm_x4(Ah[0], Ah[1], Ah[2], Ah[3], ahA + kt * 32u);
                    ldsm_x4(Al[0], Al[1], Al[2], Al[3], alA + kt * 32u);
                } else {
                    ldsm_x2(Ah[0], Ah[1], ahA6); Ah[2] = 0u; Ah[3] = 0u;
                    ldsm_x2(Al[0], Al[1], alA6); Al[2] = 0u; Al[3] = 0u;
                }
                #pragma unroll
                for (int n = 0; n < 4; ++n) {
                    mma_bf16(c[n], Ah[0], Ah[1], Ah[2], Ah[3], hh[2 * n], hh[2 * n + 1]);
                    mma_bf16(c[n], Ah[0], Ah[1], Ah[2], Ah[3], hl[2 * n], hl[2 * n + 1]);
                    mma_bf16(c[n], Al[0], Al[1], Al[2], Al[3], hh[2 * n], hh[2 * n + 1]);
                }
            }
            float* outb = out + (size_t)b * (L_ * D_);
            #pragma unroll
            for (int n = 0; n < 4; ++n) {
                #pragma unroll
                for (int p = 0; p < 2; ++p) {
                    int row = r0 + g + p * 8;
                    if (row < L_) {
                        int colo = nq * 32 + n * 8 + t4 * 2;
                        float2 v2 = make_float2(c[n][p * 2], c[n][p * 2 + 1]);
                        *(float2*)(outb + row * D_ + colo) = v2;
                    }
                }
            }
        }
    }
}

extern "C" void kernel_launch(void* const* d_in, const int* in_sizes, int n_in,
                              void* d_out, int out_size) {
    // metadata order: inputs, adj, mask_item, item, emb_table, a0, a1, a2, a3
    const int*   inputs = (const int*)d_in[0];
    const int*   adj    = (const int*)d_in[1];
    const float* emb    = (const float*)d_in[4];
    const float* a0     = (const float*)d_in[5];
    const float* a1     = (const float*)d_in[6];
    const float* a2     = (const float*)d_in[7];
    const float* a3     = (const float*)d_in[8];
    float* out = (float*)d_out;

    cudaFuncSetAttribute(combine_graph_kernel,
                         cudaFuncAttributeMaxDynamicSharedMemorySize, SMEM_TOTAL);

    combine_graph_kernel<<<B_, NT, SMEM_TOTAL>>>(inputs, adj, emb, a0, a1, a2, a3, out);
}

// round 15
// speedup vs baseline: 1.1238x; 1.1238x over previous
#include <cuda_runtime.h>
#include <cuda_fp16.h>
#include <cstdint>
#include <cstddef>

// CombineGraph: h = emb[inputs]; e_k = leakyrelu(einsum(bid,bjd,d->bij; h,h,a_k));
// alpha = softmax(select_by_adj(e_k, -9e15)); out = alpha @ h.
// B=512, L=100, D=128. One CTA/batch, 448 threads (14 warps), 2 CTA/SM.
// fp16 end-to-end (10-bit mantissa = tf32-class accuracy, measured 2.8e-4 analog):
// GEMM1: fp16 symmetric triangle, 28 m16n16 tiles = 2 perfect rounds; epilogue
// writes direct+mirror f32 logits to al. Softmax -> fp16 alpha in place.
// GEMM2: single-term fp16 ldmatrix GEMM (3 ldsm + 4 mma per kt).

#define B_    512
#define L_    100
#define D_    128
#define NT    448        // threads per CTA (14 warps)
#define HB    68         // h fp16 row stride (u32 words): 272B/row, ldmatrix conflict-free
#define AS    108        // al row stride (f32 words); after softmax words 0-51 = fp16 alpha
#define ADJS  104        // adj row stride (bytes)
#define NEG_INF_ -9e15f

// ---- smem byte offsets ----
#define OFF_HF   0        // h fp16: 104*68*4 = 28288
#define OFF_ATP  28288    // a packed fp16x2 uint4[64]: -> 29312
#define OFF_ADJ  29312    // adj int8 100*104: -> 39712
#define OFF_AL   39712    // alpha f32 104*108*4 = 44928: -> 84640
#define SMEM_TOTAL 84640

__device__ __forceinline__ uint32_t smem_u32(const void* p) {
    uint32_t a;
    asm("{ .reg .u64 t; cvta.to.shared.u64 t, %1; cvt.u32.u64 %0, t; }" : "=r"(a) : "l"(p));
    return a;
}
__device__ __forceinline__ unsigned pack_f16x2(float lo, float hi) {
    unsigned r; asm("cvt.rn.f16x2.f32 %0, %1, %2;" : "=r"(r) : "f"(hi), "f"(lo));
    return r;
}
__device__ __forceinline__ unsigned mulf2(unsigned a, unsigned b) {
    unsigned r; asm("mul.rn.f16x2 %0, %1, %2;" : "=r"(r) : "r"(a), "r"(b));
    return r;
}
__device__ __forceinline__ void ldsm_x4(unsigned& r0, unsigned& r1, unsigned& r2, unsigned& r3,
                                        uint32_t addr) {
    asm volatile("ldmatrix.sync.aligned.m8n8.x4.shared.b16 {%0,%1,%2,%3}, [%4];"
                 : "=r"(r0), "=r"(r1), "=r"(r2), "=r"(r3) : "r"(addr));
}
__device__ __forceinline__ void ldsm_x4t(unsigned& r0, unsigned& r1, unsigned& r2, unsigned& r3,
                                         uint32_t addr) {
    asm volatile("ldmatrix.sync.aligned.m8n8.x4.trans.shared.b16 {%0,%1,%2,%3}, [%4];"
                 : "=r"(r0), "=r"(r1), "=r"(r2), "=r"(r3) : "r"(addr));
}
__device__ __forceinline__ void ldsm_x2(unsigned& r0, unsigned& r1, uint32_t addr) {
    asm volatile("ldmatrix.sync.aligned.m8n8.x2.shared.b16 {%0,%1}, [%2];"
                 : "=r"(r0), "=r"(r1) : "r"(addr));
}
__device__ __forceinline__ void mma_f16(float* c, unsigned a0, unsigned a1,
                                        unsigned a2, unsigned a3,
                                        unsigned b0, unsigned b1) {
    asm volatile(
        "mma.sync.aligned.m16n8k16.row.col.f32.f16.f16.f32 "
        "{%0,%1,%2,%3},{%4,%5,%6,%7},{%8,%9},{%0,%1,%2,%3};\n"
        : "+f"(c[0]), "+f"(c[1]), "+f"(c[2]), "+f"(c[3])
        : "r"(a0), "r"(a1), "r"(a2), "r"(a3), "r"(b0), "r"(b1));
}

// triangle decode: jobs 0..27 -> (mt, np) with np >= mt (m16 x n16 tiles)
__device__ __forceinline__ void decode_job(int job, int& mt, int& np) {
    mt = (job >= 27) ? 6 : (job >= 25) ? 5 : (job >= 22) ? 4 :
         (job >= 18) ? 3 : (job >= 13) ? 2 : (job >= 7) ? 1 : 0;
    int base = (mt == 6) ? 27 : (mt == 5) ? 25 : (mt == 4) ? 22 :
               (mt == 3) ? 18 : (mt == 2) ? 13 : (mt == 1) ? 7 : 0;
    np = mt + (job - base);
}

// One GEMM1 tile job (mt, np>=mt). Writes direct + mirrored selected logits to al.
__device__ __forceinline__ void gemm1_job(char* smem, int mt, int np,
                                          uint32_t hf_u, int lane, int g, int t4) {
    const char*  adj_sm = smem + OFF_ADJ;
    const uint4* atp4   = (const uint4*)(smem + OFF_ATP);
    float*       al_sm  = (float*)(smem + OFF_AL);
    const int r0 = mt * 16, jc0 = np * 16;

    int ra = r0 + (lane & 15);  if (ra > 103) ra = 103;
    int rb = jc0 + (lane & 15); if (rb > 103) rb = 103;
    uint32_t a_addr = hf_u + (uint32_t)(ra * HB + ((lane >> 4) << 2)) * 4u;
    uint32_t b_addr = hf_u + (uint32_t)(rb * HB + ((lane >> 4) << 2)) * 4u;
    const uint4* pt = atp4 + t4;

    float c[2][4][4];
    #pragma unroll
    for (int nn = 0; nn < 2; ++nn)
        #pragma unroll
        for (int k = 0; k < 4; ++k)
            #pragma unroll
            for (int p = 0; p < 4; ++p) c[nn][k][p] = 0.f;

    #pragma unroll 2
    for (int ks = 0; ks < 8; ++ks) {
        unsigned A0, A1, A2, A3, B0, B1, B2, B3;
        ldsm_x4(A0, A1, A2, A3, a_addr + ks * 32u);
        ldsm_x4(B0, B1, B2, B3, b_addr + ks * 32u);   // nn0:(B0,B2) nn1:(B1,B3)
        uint4 ap0 = pt[ks * 8];
        uint4 ap1 = pt[ks * 8 + 4];
        mma_f16(c[0][0], A0, A1, A2, A3, mulf2(B0, ap0.x), mulf2(B2, ap1.x));
        mma_f16(c[0][1], A0, A1, A2, A3, mulf2(B0, ap0.y), mulf2(B2, ap1.y));
        mma_f16(c[0][2], A0, A1, A2, A3, mulf2(B0, ap0.z), mulf2(B2, ap1.z));
        mma_f16(c[0][3], A0, A1, A2, A3, mulf2(B0, ap0.w), mulf2(B2, ap1.w));
        mma_f16(c[1][0], A0, A1, A2, A3, mulf2(B1, ap0.x), mulf2(B3, ap1.x));
        mma_f16(c[1][1], A0, A1, A2, A3, mulf2(B1, ap0.y), mulf2(B3, ap1.y));
        mma_f16(c[1][2], A0, A1, A2, A3, mulf2(B1, ap0.z), mulf2(B3, ap1.z));
        mma_f16(c[1][3], A0, A1, A2, A3, mulf2(B1, ap0.w), mulf2(B3, ap1.w));
    }

    // epilogue: select by adj (direct) and adj^T (mirror), leaky-relu, write al (f32)
    #pragma unroll
    for (int nn = 0; nn < 2; ++nn) {
        int col0 = jc0 + 8 * nn + 2 * t4;
        #pragma unroll
        for (int hf = 0; hf < 2; ++hf) {
            int row = r0 + g + 8 * hf;
            float vD[2], vM[2];
            #pragma unroll
            for (int e = 0; e < 2; ++e) {
                int col = col0 + e;
                int p = 2 * hf + e;
                float xD = NEG_INF_, xM = NEG_INF_;
                if (row < L_ && col < L_) {
                    int t = adj_sm[row * ADJS + col];
                    float x = (t == 1) ? c[nn][0][p] : (t == 2) ? c[nn][1][p] :
                              (t == 3) ? c[nn][2][p] : (t == 4) ? c[nn][3][p] : 0.f;
                    x = (x > 0.f) ? x : 0.2f * x;
                    xD = t ? x : NEG_INF_;
                    int tm = adj_sm[col * ADJS + row];
                    float y = (tm == 1) ? c[nn][0][p] : (tm == 2) ? c[nn][1][p] :
                              (tm == 3) ? c[nn][2][p] : (tm == 4) ? c[nn][3][p] : 0.f;
                    y = (y > 0.f) ? y : 0.2f * y;
                    xM = tm ? y : NEG_INF_;
                }
                vD[e] = xD; vM[e] = xM;
            }
            if (row < 104 && col0 < 104)   // direct (upper-triangle tile cell)
                *(float2*)(al_sm + row * AS + col0) = make_float2(vD[0], vD[1]);
            if (np > mt && row < L_) {     // mirror into strictly-lower tiles
                if (col0 < L_)     al_sm[col0 * AS + row]       = vM[0];
                if (col0 + 1 < L_) al_sm[(col0 + 1) * AS + row] = vM[1];
            }
        }
    }
}

__global__ __launch_bounds__(NT, 2)
void combine_graph_kernel(const int* __restrict__ inputs,
                          const int* __restrict__ adj,
                          const float* __restrict__ emb,
                          const float* __restrict__ a0p,
                          const float* __restrict__ a1p,
                          const float* __restrict__ a2p,
                          const float* __restrict__ a3p,
                          float* __restrict__ out)
{
    extern __shared__ char smem[];
    unsigned* hf_sm  = (unsigned*)(smem + OFF_HF);
    unsigned* atp_sm = (unsigned*)(smem + OFF_ATP);
    char*     adj_sm = smem + OFF_ADJ;
    float*    al_sm  = (float*)(smem + OFF_AL);
    unsigned* al32   = (unsigned*)(smem + OFF_AL);
    const uint32_t hf_u = smem_u32(smem + OFF_HF);
    const uint32_t al_u = smem_u32(smem + OFF_AL);

    const int b    = blockIdx.x;
    const int tid  = threadIdx.x;
    const int w    = tid >> 5;
    const int lane = tid & 31;
    const int g    = lane >> 2;
    const int t4   = lane & 3;

    const int* inp  = inputs + b * L_;
    const int* adjb = adj + (size_t)b * (L_ * L_);

    // ---------------- phase 0: loads ----------------
    if (tid < 256) {   // atp[wd] = {pack(a0),pack(a1),pack(a2),pack(a3)} for word wd
        int wd = tid & 63, k = tid >> 6;
        const float* ap = (k == 0) ? a0p : (k == 1) ? a1p : (k == 2) ? a2p : a3p;
        ((unsigned*)((uint4*)atp_sm + wd))[k] = pack_f16x2(ap[2 * wd], ap[2 * wd + 1]);
    }
    // embedding gather -> h fp16; rows 100..103 zero
    for (int e = tid; e < 104 * 32; e += NT) {
        int r = e >> 5, q = e & 31;
        float4 v = make_float4(0.f, 0.f, 0.f, 0.f);
        if (r < L_) {
            int id = inp[r];
            v = ((const float4*)(emb + (size_t)id * D_))[q];
        }
        *(uint2*)(hf_sm + r * HB + 2 * q) = make_uint2(pack_f16x2(v.x, v.y),
                                                       pack_f16x2(v.z, v.w));
    }
    // adj -> int8
    for (int e = tid; e < 2500; e += NT) {
        int i = e / 25, c = e % 25;
        int4 v = ((const int4*)(adjb + i * 100))[c];
        unsigned p = (unsigned)(v.x & 0xff) | ((unsigned)(v.y & 0xff) << 8)
                   | ((unsigned)(v.z & 0xff) << 16) | ((unsigned)(v.w & 0xff) << 24);
        *(unsigned*)(adj_sm + i * ADJS + c * 4) = p;
    }
    __syncthreads();

    // ---- GEMM1: 28 upper-triangle m16n16 tiles = 2 perfect rounds on 14 warps ----
    {
        int mt, np;
        decode_job(w, mt, np);
        gemm1_job(smem, mt, np, hf_u, lane, g, t4);
        decode_job(w + 14, mt, np);
        gemm1_job(smem, mt, np, hf_u, lane, g, t4);
    }
    __syncthreads();

    // -------- softmax: al f32 row -> fp16 alpha in words 0..51 (in place) --------
    for (int i = w; i < L_; i += 14) {
        float4 x = make_float4(NEG_INF_, NEG_INF_, NEG_INF_, NEG_INF_);
        if (lane < 26) x = *(const float4*)(al_sm + i * AS + 4 * lane);
        float mx = fmaxf(fmaxf(x.x, x.y), fmaxf(x.z, x.w));
        #pragma unroll
        for (int o = 16; o > 0; o >>= 1) mx = fmaxf(mx, __shfl_xor_sync(0xffffffffu, mx, o));
        float4 ev = make_float4(0.f, 0.f, 0.f, 0.f);
        if (lane < 25) {   // cols 100..103 masked out
            ev.x = __expf(x.x - mx); ev.y = __expf(x.y - mx);
            ev.z = __expf(x.z - mx); ev.w = __expf(x.w - mx);
        }
        float s = (ev.x + ev.y) + (ev.z + ev.w);
        #pragma unroll
        for (int o = 16; o > 0; o >>= 1) s += __shfl_xor_sync(0xffffffffu, s, o);
        float inv = 1.f / s;
        if (lane < 26) {   // warp-synchronous: all reads done before these writes
            float a0 = ev.x * inv, a1 = ev.y * inv, a2 = ev.z * inv, a3 = ev.w * inv;
            *(uint2*)(al32 + i * AS + 2 * lane) = make_uint2(pack_f16x2(a0, a1),
                                                             pack_f16x2(a2, a3));
        }
    }
    // zero fp16-alpha rows 100..103 (GEMM2 A-fragment clamp reads row 103)
    if (tid < 208) {
        int rr = tid / 52, cc = tid % 52;
        al32[(100 + rr) * AS + cc] = 0u;
    }
    __syncthreads();

    // ---------- GEMM2: out = alpha @ h (fp16, ldmatrix, 2 perfect rounds) ----------
    #pragma unroll
    for (int kk = 0; kk < 2; ++kk) {
        int job = w + 14 * kk;    // 28 jobs = 2 perfect rounds
        {
            int mt16 = job >> 2;          // 0..6
            int nq   = job & 3;           // n32 quarter of D
            const int r0 = mt16 * 16;

            int rowA = r0 + (lane & 15); if (rowA > 103) rowA = 103;
            uint32_t ahA  = al_u + (uint32_t)(rowA * (AS * 4)) + (uint32_t)((lane >> 4) << 4);
            uint32_t ahA6 = al_u + (uint32_t)(rowA * (AS * 4)) + 192u;
            const uint32_t bcol = (uint32_t)(nq * 64) + (uint32_t)((lane >> 4) << 4);

            float c[4][4];
            #pragma unroll
            for (int n = 0; n < 4; ++n)
                #pragma unroll
                for (int p = 0; p < 4; ++p) c[n][p] = 0.f;

            #pragma unroll 1
            for (int kt = 0; kt < 7; ++kt) {
                int jr = kt * 16 + (lane & 15); if (jr > 103) jr = 103;
                uint32_t boff = (uint32_t)(jr * (HB * 4)) + bcol;
                unsigned hh[8];
                ldsm_x4t(hh[0], hh[1], hh[2], hh[3], hf_u + boff);
                ldsm_x4t(hh[4], hh[5], hh[6], hh[7], hf_u + boff + 32u);
                unsigned A[4];
                if (kt < 6) {
                    ldsm_x4(A[0], A[1], A[2], A[3], ahA + kt * 32u);
                } else {
                    ldsm_x2(A[0], A[1], ahA6); A[2] = 0u; A[3] = 0u;
                }
                #pragma unroll
                for (int n = 0; n < 4; ++n)
                    mma_f16(c[n], A[0], A[1], A[2], A[3], hh[2 * n], hh[2 * n + 1]);
            }
            float* outb = out + (size_t)b * (L_ * D_);
            #pragma unroll
            for (int n = 0; n < 4; ++n) {
                #pragma unroll
                for (int p = 0; p < 2; ++p) {
                    int row = r0 + g + p * 8;
                    if (row < L_) {
                        int colo = nq * 32 + n * 8 + t4 * 2;
                        float2 v2 = make_float2(c[n][p * 2], c[n][p * 2 + 1]);
                        *(float2*)(outb + row * D_ + colo) = v2;
                    }
                }
            }
        }
    }
}

extern "C" void kernel_launch(void* const* d_in, const int* in_sizes, int n_in,
                              void* d_out, int out_size) {
    // metadata order: inputs, adj, mask_item, item, emb_table, a0, a1, a2, a3
    const int*   inputs = (const int*)d_in[0];
    const int*   adj    = (const int*)d_in[1];
    const float* emb    = (const float*)d_in[4];
    const float* a0     = (const float*)d_in[5];
    const float* a1     = (const float*)d_in[6];
    const float* a2     = (const float*)d_in[7];
    const float* a3     = (const float*)d_in[8];
    float* out = (float*)d_out;

    cudaFuncSetAttribute(combine_graph_kernel,
                         cudaFuncAttributeMaxDynamicSharedMemorySize, SMEM_TOTAL);

    combine_graph_kernel<<<B_, NT, SMEM_TOTAL>>>(inputs, adj, emb, a0, a1, a2, a3, out);
}

// round 16
// speedup vs baseline: 1.1296x; 1.0052x over previous
#include <cuda_runtime.h>
#include <cuda_fp16.h>
#include <cstdint>
#include <cstddef>

// CombineGraph: h = emb[inputs]; e_k = leakyrelu(einsum(bid,bjd,d->bij; h,h,a_k));
// alpha = softmax(select_by_adj(e_k, -9e15)); out = alpha @ h.
// B=512, L=100, D=128. One CTA/batch, 512 threads (16 warps), 2 CTA/SM (32 warps/SM).
// fp16 end-to-end (10-bit mantissa = tf32-class accuracy, measured 2.8e-4):
// GEMM1: fp16 symmetric triangle, 28 m16n16 tiles (rounds 16+12); epilogue
// writes direct+mirror f32 logits to al. Softmax -> fp16 alpha in place.
// GEMM2: single-term fp16 ldmatrix GEMM (3 ldsm + 4 mma per kt), rounds 16+12.

#define B_    512
#define L_    100
#define D_    128
#define NT    512        // threads per CTA (16 warps)
#define HB    68         // h fp16 row stride (u32 words): 272B/row, ldmatrix conflict-free
#define AS    108        // al row stride (f32 words); after softmax words 0-51 = fp16 alpha
#define ADJS  104        // adj row stride (bytes)
#define NEG_INF_ -9e15f

// ---- smem byte offsets ----
#define OFF_HF   0        // h fp16: 104*68*4 = 28288
#define OFF_ATP  28288    // a packed fp16x2 uint4[64]: -> 29312
#define OFF_ADJ  29312    // adj int8 100*104: -> 39712
#define OFF_AL   39712    // alpha f32 104*108*4 = 44928: -> 84640
#define SMEM_TOTAL 84640

__device__ __forceinline__ uint32_t smem_u32(const void* p) {
    uint32_t a;
    asm("{ .reg .u64 t; cvta.to.shared.u64 t, %1; cvt.u32.u64 %0, t; }" : "=r"(a) : "l"(p));
    return a;
}
__device__ __forceinline__ unsigned pack_f16x2(float lo, float hi) {
    unsigned r; asm("cvt.rn.f16x2.f32 %0, %1, %2;" : "=r"(r) : "f"(hi), "f"(lo));
    return r;
}
__device__ __forceinline__ unsigned mulf2(unsigned a, unsigned b) {
    unsigned r; asm("mul.rn.f16x2 %0, %1, %2;" : "=r"(r) : "r"(a), "r"(b));
    return r;
}
__device__ __forceinline__ void ldsm_x4(unsigned& r0, unsigned& r1, unsigned& r2, unsigned& r3,
                                        uint32_t addr) {
    asm volatile("ldmatrix.sync.aligned.m8n8.x4.shared.b16 {%0,%1,%2,%3}, [%4];"
                 : "=r"(r0), "=r"(r1), "=r"(r2), "=r"(r3) : "r"(addr));
}
__device__ __forceinline__ void ldsm_x4t(unsigned& r0, unsigned& r1, unsigned& r2, unsigned& r3,
                                         uint32_t addr) {
    asm volatile("ldmatrix.sync.aligned.m8n8.x4.trans.shared.b16 {%0,%1,%2,%3}, [%4];"
                 : "=r"(r0), "=r"(r1), "=r"(r2), "=r"(r3) : "r"(addr));
}
__device__ __forceinline__ void ldsm_x2(unsigned& r0, unsigned& r1, uint32_t addr) {
    asm volatile("ldmatrix.sync.aligned.m8n8.x2.shared.b16 {%0,%1}, [%2];"
                 : "=r"(r0), "=r"(r1) : "r"(addr));
}
__device__ __forceinline__ void mma_f16(float* c, unsigned a0, unsigned a1,
                                        unsigned a2, unsigned a3,
                                        unsigned b0, unsigned b1) {
    asm volatile(
        "mma.sync.aligned.m16n8k16.row.col.f32.f16.f16.f32 "
        "{%0,%1,%2,%3},{%4,%5,%6,%7},{%8,%9},{%0,%1,%2,%3};\n"
        : "+f"(c[0]), "+f"(c[1]), "+f"(c[2]), "+f"(c[3])
        : "r"(a0), "r"(a1), "r"(a2), "r"(a3), "r"(b0), "r"(b1));
}

// triangle decode: jobs 0..27 -> (mt, np) with np >= mt (m16 x n16 tiles)
__device__ __forceinline__ void decode_job(int job, int& mt, int& np) {
    mt = (job >= 27) ? 6 : (job >= 25) ? 5 : (job >= 22) ? 4 :
         (job >= 18) ? 3 : (job >= 13) ? 2 : (job >= 7) ? 1 : 0;
    int base = (mt == 6) ? 27 : (mt == 5) ? 25 : (mt == 4) ? 22 :
               (mt == 3) ? 18 : (mt == 2) ? 13 : (mt == 1) ? 7 : 0;
    np = mt + (job - base);
}

// One GEMM1 tile job (mt, np>=mt). Writes direct + mirrored selected logits to al.
__device__ __forceinline__ void gemm1_job(char* smem, int mt, int np,
                                          uint32_t hf_u, int lane, int g, int t4) {
    const char*  adj_sm = smem + OFF_ADJ;
    const uint4* atp4   = (const uint4*)(smem + OFF_ATP);
    float*       al_sm  = (float*)(smem + OFF_AL);
    const int r0 = mt * 16, jc0 = np * 16;

    int ra = r0 + (lane & 15);  if (ra > 103) ra = 103;
    int rb = jc0 + (lane & 15); if (rb > 103) rb = 103;
    uint32_t a_addr = hf_u + (uint32_t)(ra * HB + ((lane >> 4) << 2)) * 4u;
    uint32_t b_addr = hf_u + (uint32_t)(rb * HB + ((lane >> 4) << 2)) * 4u;
    const uint4* pt = atp4 + t4;

    float c[2][4][4];
    #pragma unroll
    for (int nn = 0; nn < 2; ++nn)
        #pragma unroll
        for (int k = 0; k < 4; ++k)
            #pragma unroll
            for (int p = 0; p < 4; ++p) c[nn][k][p] = 0.f;

    #pragma unroll 2
    for (int ks = 0; ks < 8; ++ks) {
        unsigned A0, A1, A2, A3, B0, B1, B2, B3;
        ldsm_x4(A0, A1, A2, A3, a_addr + ks * 32u);
        ldsm_x4(B0, B1, B2, B3, b_addr + ks * 32u);   // nn0:(B0,B2) nn1:(B1,B3)
        uint4 ap0 = pt[ks * 8];
        uint4 ap1 = pt[ks * 8 + 4];
        mma_f16(c[0][0], A0, A1, A2, A3, mulf2(B0, ap0.x), mulf2(B2, ap1.x));
        mma_f16(c[0][1], A0, A1, A2, A3, mulf2(B0, ap0.y), mulf2(B2, ap1.y));
        mma_f16(c[0][2], A0, A1, A2, A3, mulf2(B0, ap0.z), mulf2(B2, ap1.z));
        mma_f16(c[0][3], A0, A1, A2, A3, mulf2(B0, ap0.w), mulf2(B2, ap1.w));
        mma_f16(c[1][0], A0, A1, A2, A3, mulf2(B1, ap0.x), mulf2(B3, ap1.x));
        mma_f16(c[1][1], A0, A1, A2, A3, mulf2(B1, ap0.y), mulf2(B3, ap1.y));
        mma_f16(c[1][2], A0, A1, A2, A3, mulf2(B1, ap0.z), mulf2(B3, ap1.z));
        mma_f16(c[1][3], A0, A1, A2, A3, mulf2(B1, ap0.w), mulf2(B3, ap1.w));
    }

    // epilogue: select by adj (direct) and adj^T (mirror), leaky-relu, write al (f32)
    #pragma unroll
    for (int nn = 0; nn < 2; ++nn) {
        int col0 = jc0 + 8 * nn + 2 * t4;
        #pragma unroll
        for (int hf = 0; hf < 2; ++hf) {
            int row = r0 + g + 8 * hf;
            float vD[2], vM[2];
            #pragma unroll
            for (int e = 0; e < 2; ++e) {
                int col = col0 + e;
                int p = 2 * hf + e;
                float xD = NEG_INF_, xM = NEG_INF_;
                if (row < L_ && col < L_) {
                    int t = adj_sm[row * ADJS + col];
                    float x = (t == 1) ? c[nn][0][p] : (t == 2) ? c[nn][1][p] :
                              (t == 3) ? c[nn][2][p] : (t == 4) ? c[nn][3][p] : 0.f;
                    x = (x > 0.f) ? x : 0.2f * x;
                    xD = t ? x : NEG_INF_;
                    int tm = adj_sm[col * ADJS + row];
                    float y = (tm == 1) ? c[nn][0][p] : (tm == 2) ? c[nn][1][p] :
                              (tm == 3) ? c[nn][2][p] : (tm == 4) ? c[nn][3][p] : 0.f;
                    y = (y > 0.f) ? y : 0.2f * y;
                    xM = tm ? y : NEG_INF_;
                }
                vD[e] = xD; vM[e] = xM;
            }
            if (row < 104 && col0 < 104)   // direct (upper-triangle tile cell)
                *(float2*)(al_sm + row * AS + col0) = make_float2(vD[0], vD[1]);
            if (np > mt && row < L_) {     // mirror into strictly-lower tiles
                if (col0 < L_)     al_sm[col0 * AS + row]       = vM[0];
                if (col0 + 1 < L_) al_sm[(col0 + 1) * AS + row] = vM[1];
            }
        }
    }
}

__global__ __launch_bounds__(NT, 2)
void combine_graph_kernel(const int* __restrict__ inputs,
                          const int* __restrict__ adj,
                          const float* __restrict__ emb,
                          const float* __restrict__ a0p,
                          const float* __restrict__ a1p,
                          const float* __restrict__ a2p,
                          const float* __restrict__ a3p,
                          float* __restrict__ out)
{
    extern __shared__ char smem[];
    unsigned* hf_sm  = (unsigned*)(smem + OFF_HF);
    unsigned* atp_sm = (unsigned*)(smem + OFF_ATP);
    char*     adj_sm = smem + OFF_ADJ;
    float*    al_sm  = (float*)(smem + OFF_AL);
    unsigned* al32   = (unsigned*)(smem + OFF_AL);
    const uint32_t hf_u = smem_u32(smem + OFF_HF);
    const uint32_t al_u = smem_u32(smem + OFF_AL);

    const int b    = blockIdx.x;
    const int tid  = threadIdx.x;
    const int w    = tid >> 5;
    const int lane = tid & 31;
    const int g    = lane >> 2;
    const int t4   = lane & 3;

    const int* inp  = inputs + b * L_;
    const int* adjb = adj + (size_t)b * (L_ * L_);

    // ---------------- phase 0: loads ----------------
    if (tid < 256) {   // atp[wd] = {pack(a0),pack(a1),pack(a2),pack(a3)} for word wd
        int wd = tid & 63, k = tid >> 6;
        const float* ap = (k == 0) ? a0p : (k == 1) ? a1p : (k == 2) ? a2p : a3p;
        ((unsigned*)((uint4*)atp_sm + wd))[k] = pack_f16x2(ap[2 * wd], ap[2 * wd + 1]);
    }
    // embedding gather -> h fp16; rows 100..103 zero
    for (int e = tid; e < 104 * 32; e += NT) {
        int r = e >> 5, q = e & 31;
        float4 v = make_float4(0.f, 0.f, 0.f, 0.f);
        if (r < L_) {
            int id = inp[r];
            v = ((const float4*)(emb + (size_t)id * D_))[q];
        }
        *(uint2*)(hf_sm + r * HB + 2 * q) = make_uint2(pack_f16x2(v.x, v.y),
                                                       pack_f16x2(v.z, v.w));
    }
    // adj -> int8
    for (int e = tid; e < 2500; e += NT) {
        int i = e / 25, c = e % 25;
        int4 v = ((const int4*)(adjb + i * 100))[c];
        unsigned p = (unsigned)(v.x & 0xff) | ((unsigned)(v.y & 0xff) << 8)
                   | ((unsigned)(v.z & 0xff) << 16) | ((unsigned)(v.w & 0xff) << 24);
        *(unsigned*)(adj_sm + i * ADJS + c * 4) = p;
    }
    __syncthreads();

    // ---- GEMM1: 28 upper-triangle m16n16 tiles over 16 warps (rounds 16 + 12) ----
    {
        int mt, np;
        decode_job(w, mt, np);
        gemm1_job(smem, mt, np, hf_u, lane, g, t4);
        if (w + 16 < 28) {
            decode_job(w + 16, mt, np);
            gemm1_job(smem, mt, np, hf_u, lane, g, t4);
        }
    }
    __syncthreads();

    // -------- softmax: al f32 row -> fp16 alpha in words 0..51 (in place) --------
    for (int i = w; i < L_; i += 16) {
        float4 x = make_float4(NEG_INF_, NEG_INF_, NEG_INF_, NEG_INF_);
        if (lane < 26) x = *(const float4*)(al_sm + i * AS + 4 * lane);
        float mx = fmaxf(fmaxf(x.x, x.y), fmaxf(x.z, x.w));
        #pragma unroll
        for (int o = 16; o > 0; o >>= 1) mx = fmaxf(mx, __shfl_xor_sync(0xffffffffu, mx, o));
        float4 ev = make_float4(0.f, 0.f, 0.f, 0.f);
        if (lane < 25) {   // cols 100..103 masked out
            ev.x = __expf(x.x - mx); ev.y = __expf(x.y - mx);
            ev.z = __expf(x.z - mx); ev.w = __expf(x.w - mx);
        }
        float s = (ev.x + ev.y) + (ev.z + ev.w);
        #pragma unroll
        for (int o = 16; o > 0; o >>= 1) s += __shfl_xor_sync(0xffffffffu, s, o);
        float inv = 1.f / s;
        if (lane < 26) {   // warp-synchronous: all reads done before these writes
            float a0 = ev.x * inv, a1 = ev.y * inv, a2 = ev.z * inv, a3 = ev.w * inv;
            *(uint2*)(al32 + i * AS + 2 * lane) = make_uint2(pack_f16x2(a0, a1),
                                                             pack_f16x2(a2, a3));
        }
    }
    // zero fp16-alpha rows 100..103 (GEMM2 A-fragment clamp reads row 103)
    if (tid < 208) {
        int rr = tid / 52, cc = tid % 52;
        al32[(100 + rr) * AS + cc] = 0u;
    }
    __syncthreads();

    // ---------- GEMM2: out = alpha @ h (fp16, ldmatrix, rounds 16 + 12) ----------
    #pragma unroll
    for (int kk = 0; kk < 2; ++kk) {
        int job = w + 16 * kk;
        if (job < 28) {
            int mt16 = job >> 2;          // 0..6
            int nq   = job & 3;           // n32 quarter of D
            const int r0 = mt16 * 16;

            int rowA = r0 + (lane & 15); if (rowA > 103) rowA = 103;
            uint32_t ahA  = al_u + (uint32_t)(rowA * (AS * 4)) + (uint32_t)((lane >> 4) << 4);
            uint32_t ahA6 = al_u + (uint32_t)(rowA * (AS * 4)) + 192u;
            const uint32_t bcol = (uint32_t)(nq * 64) + (uint32_t)((lane >> 4) << 4);

            float c[4][4];
            #pragma unroll
            for (int n = 0; n < 4; ++n)
                #pragma unroll
                for (int p = 0; p < 4; ++p) c[n][p] = 0.f;

            #pragma unroll 1
            for (int kt = 0; kt < 7; ++kt) {
                int jr = kt * 16 + (lane & 15); if (jr > 103) jr = 103;
                uint32_t boff = (uint32_t)(jr * (HB * 4)) + bcol;
                unsigned hh[8];
                ldsm_x4t(hh[0], hh[1], hh[2], hh[3], hf_u + boff);
                ldsm_x4t(hh[4], hh[5], hh[6], hh[7], hf_u + boff + 32u);
                unsigned A[4];
                if (kt < 6) {
                    ldsm_x4(A[0], A[1], A[2], A[3], ahA + kt * 32u);
                } else {
                    ldsm_x2(A[0], A[1], ahA6); A[2] = 0u; A[3] = 0u;
                }
                #pragma unroll
                for (int n = 0; n < 4; ++n)
                    mma_f16(c[n], A[0], A[1], A[2], A[3], hh[2 * n], hh[2 * n + 1]);
            }
            float* outb = out + (size_t)b * (L_ * D_);
            #pragma unroll
            for (int n = 0; n < 4; ++n) {
                #pragma unroll
                for (int p = 0; p < 2; ++p) {
                    int row = r0 + g + p * 8;
                    if (row < L_) {
                        int colo = nq * 32 + n * 8 + t4 * 2;
                        float2 v2 = make_float2(c[n][p * 2], c[n][p * 2 + 1]);
                        *(float2*)(outb + row * D_ + colo) = v2;
                    }
                }
            }
        }
    }
}

extern "C" void kernel_launch(void* const* d_in, const int* in_sizes, int n_in,
                              void* d_out, int out_size) {
    // metadata order: inputs, adj, mask_item, item, emb_table, a0, a1, a2, a3
    const int*   inputs = (const int*)d_in[0];
    const int*   adj    = (const int*)d_in[1];
    const float* emb    = (const float*)d_in[4];
    const float* a0     = (const float*)d_in[5];
    const float* a1     = (const float*)d_in[6];
    const float* a2     = (const float*)d_in[7];
    const float* a3     = (const float*)d_in[8];
    float* out = (float*)d_out;

    cudaFuncSetAttribute(combine_graph_kernel,
                         cudaFuncAttributeMaxDynamicSharedMemorySize, SMEM_TOTAL);

    combine_graph_kernel<<<B_, NT, SMEM_TOTAL>>>(inputs, adj, emb, a0, a1, a2, a3, out);
}

// round 17
// speedup vs baseline: 1.3529x; 1.1977x over previous
#include <cuda_runtime.h>
#include <cuda_fp16.h>
#include <cstdint>
#include <cstddef>

// CombineGraph: h = emb[inputs]; e_k = leakyrelu(einsum(bid,bjd,d->bij; h,h,a_k));
// alpha = softmax(select_by_adj(e_k, -9e15)); out = alpha @ h.
// B=512, L=100, D=128. One CTA/batch, 512 threads, 2 CTA/SM.
// fp16 end-to-end. GEMM1: fp16 in / fp16 accum symmetric triangle (28 m16n16
// tiles); adj prefetched into regs before the mma loop; packed hmax2 leaky;
// diagonal tiles skip mirror. Softmax -> fp16 alpha in place (f32 al staging).
// GEMM2: single-term fp16 ldmatrix GEMM.

#define B_    512
#define L_    100
#define D_    128
#define NT    512        // threads per CTA (16 warps)
#define HB    68         // h fp16 row stride (u32 words): 272B/row, ldmatrix conflict-free
#define AS    108        // al row stride (f32 words); after softmax words 0-51 = fp16 alpha
#define ADJS  104        // adj row stride (bytes)
#define NEG_INF_ -9e15f

// ---- smem byte offsets ----
#define OFF_HF   0        // h fp16: 104*68*4 = 28288
#define OFF_ATP  28288    // a packed fp16x2 uint4[64]: -> 29312
#define OFF_ADJ  29312    // adj int8 100*104: -> 39712
#define OFF_AL   39712    // alpha f32 104*108*4 = 44928: -> 84640
#define SMEM_TOTAL 84640

__device__ __forceinline__ uint32_t smem_u32(const void* p) {
    uint32_t a;
    asm("{ .reg .u64 t; cvta.to.shared.u64 t, %1; cvt.u32.u64 %0, t; }" : "=r"(a) : "l"(p));
    return a;
}
__device__ __forceinline__ unsigned pack_f16x2(float lo, float hi) {
    unsigned r; asm("cvt.rn.f16x2.f32 %0, %1, %2;" : "=r"(r) : "f"(hi), "f"(lo));
    return r;
}
__device__ __forceinline__ unsigned mulf2(unsigned a, unsigned b) {
    unsigned r; asm("mul.rn.f16x2 %0, %1, %2;" : "=r"(r) : "r"(a), "r"(b));
    return r;
}
__device__ __forceinline__ unsigned maxf2(unsigned a, unsigned b) {
    unsigned r; asm("max.f16x2 %0, %1, %2;" : "=r"(r) : "r"(a), "r"(b));
    return r;
}
__device__ __forceinline__ float half_ex(unsigned u, int e) {
    __half2 h = *reinterpret_cast<__half2*>(&u);
    return e ? __high2float(h) : __low2float(h);
}
__device__ __forceinline__ void ldsm_x4(unsigned& r0, unsigned& r1, unsigned& r2, unsigned& r3,
                                        uint32_t addr) {
    asm volatile("ldmatrix.sync.aligned.m8n8.x4.shared.b16 {%0,%1,%2,%3}, [%4];"
                 : "=r"(r0), "=r"(r1), "=r"(r2), "=r"(r3) : "r"(addr));
}
__device__ __forceinline__ void ldsm_x4t(unsigned& r0, unsigned& r1, unsigned& r2, unsigned& r3,
                                         uint32_t addr) {
    asm volatile("ldmatrix.sync.aligned.m8n8.x4.trans.shared.b16 {%0,%1,%2,%3}, [%4];"
                 : "=r"(r0), "=r"(r1), "=r"(r2), "=r"(r3) : "r"(addr));
}
__device__ __forceinline__ void ldsm_x2(unsigned& r0, unsigned& r1, uint32_t addr) {
    asm volatile("ldmatrix.sync.aligned.m8n8.x2.shared.b16 {%0,%1}, [%2];"
                 : "=r"(r0), "=r"(r1) : "r"(addr));
}
// fp16-accumulator mma: D(2 regs) = A(4) * B(2) + D
__device__ __forceinline__ void mma_f16a(unsigned* c, unsigned a0, unsigned a1,
                                         unsigned a2, unsigned a3,
                                         unsigned b0, unsigned b1) {
    asm volatile(
        "mma.sync.aligned.m16n8k16.row.col.f16.f16.f16.f16 "
        "{%0,%1},{%2,%3,%4,%5},{%6,%7},{%0,%1};\n"
        : "+r"(c[0]), "+r"(c[1])
        : "r"(a0), "r"(a1), "r"(a2), "r"(a3), "r"(b0), "r"(b1));
}
// f32-accumulator mma (GEMM2)
__device__ __forceinline__ void mma_f16(float* c, unsigned a0, unsigned a1,
                                        unsigned a2, unsigned a3,
                                        unsigned b0, unsigned b1) {
    asm volatile(
        "mma.sync.aligned.m16n8k16.row.col.f32.f16.f16.f32 "
        "{%0,%1,%2,%3},{%4,%5,%6,%7},{%8,%9},{%0,%1,%2,%3};\n"
        : "+f"(c[0]), "+f"(c[1]), "+f"(c[2]), "+f"(c[3])
        : "r"(a0), "r"(a1), "r"(a2), "r"(a3), "r"(b0), "r"(b1));
}

// triangle decode: jobs 0..27 -> (mt, np) with np >= mt (m16 x n16 tiles)
__device__ __forceinline__ void decode_job(int job, int& mt, int& np) {
    mt = (job >= 27) ? 6 : (job >= 25) ? 5 : (job >= 22) ? 4 :
         (job >= 18) ? 3 : (job >= 13) ? 2 : (job >= 7) ? 1 : 0;
    int base = (mt == 6) ? 27 : (mt == 5) ? 25 : (mt == 4) ? 22 :
               (mt == 3) ? 18 : (mt == 2) ? 13 : (mt == 1) ? 7 : 0;
    np = mt + (job - base);
}

// One GEMM1 tile job (mt, np>=mt). Writes direct + mirrored selected logits to al.
__device__ __forceinline__ void gemm1_job(char* smem, int mt, int np,
                                          uint32_t hf_u, int lane, int g, int t4) {
    const char*  adj_sm = smem + OFF_ADJ;
    const uint4* atp4   = (const uint4*)(smem + OFF_ATP);
    float*       al_sm  = (float*)(smem + OFF_AL);
    const int r0 = mt * 16, jc0 = np * 16;
    const bool do_mirror = (np > mt);

    int ra = r0 + (lane & 15);  if (ra > 103) ra = 103;
    int rb = jc0 + (lane & 15); if (rb > 103) rb = 103;
    uint32_t a_addr = hf_u + (uint32_t)(ra * HB + ((lane >> 4) << 2)) * 4u;
    uint32_t b_addr = hf_u + (uint32_t)(rb * HB + ((lane >> 4) << 2)) * 4u;
    const uint4* pt = atp4 + t4;

    // ---- adj prefetch (latency hidden under the mma loop) ----
    unsigned short dirt[2][2];
    unsigned char  mirt[2][2][2];
    #pragma unroll
    for (int hf = 0; hf < 2; ++hf) {
        int row  = r0 + g + 8 * hf;
        int radj = (row > 99) ? 99 : row;
        #pragma unroll
        for (int nn = 0; nn < 2; ++nn) {
            int col0 = jc0 + 8 * nn + 2 * t4;
            dirt[nn][hf] = *(const unsigned short*)(adj_sm + radj * ADJS + col0);
            if (do_mirror) {
                #pragma unroll
                for (int e = 0; e < 2; ++e) {
                    int colc = col0 + e; if (colc > 99) colc = 99;
                    mirt[nn][hf][e] = (unsigned char)adj_sm[colc * ADJS + radj];
                }
            }
        }
    }

    unsigned c[2][4][2];
    #pragma unroll
    for (int nn = 0; nn < 2; ++nn)
        #pragma unroll
        for (int k = 0; k < 4; ++k) { c[nn][k][0] = 0u; c[nn][k][1] = 0u; }

    #pragma unroll 2
    for (int ks = 0; ks < 8; ++ks) {
        unsigned A0, A1, A2, A3, B0, B1, B2, B3;
        ldsm_x4(A0, A1, A2, A3, a_addr + ks * 32u);
        ldsm_x4(B0, B1, B2, B3, b_addr + ks * 32u);   // nn0:(B0,B2) nn1:(B1,B3)
        uint4 ap0 = pt[ks * 8];
        uint4 ap1 = pt[ks * 8 + 4];
        mma_f16a(c[0][0], A0, A1, A2, A3, mulf2(B0, ap0.x), mulf2(B2, ap1.x));
        mma_f16a(c[0][1], A0, A1, A2, A3, mulf2(B0, ap0.y), mulf2(B2, ap1.y));
        mma_f16a(c[0][2], A0, A1, A2, A3, mulf2(B0, ap0.z), mulf2(B2, ap1.z));
        mma_f16a(c[0][3], A0, A1, A2, A3, mulf2(B0, ap0.w), mulf2(B2, ap1.w));
        mma_f16a(c[1][0], A0, A1, A2, A3, mulf2(B1, ap0.x), mulf2(B3, ap1.x));
        mma_f16a(c[1][1], A0, A1, A2, A3, mulf2(B1, ap0.y), mulf2(B3, ap1.y));
        mma_f16a(c[1][2], A0, A1, A2, A3, mulf2(B1, ap0.z), mulf2(B3, ap1.z));
        mma_f16a(c[1][3], A0, A1, A2, A3, mulf2(B1, ap0.w), mulf2(B3, ap1.w));
    }

    // ---- epilogue: packed leaky, reg-prefetched adj select, write al (f32) ----
    const unsigned C02 = 0x32663266u;   // {0.2, 0.2} fp16
    #pragma unroll
    for (int nn = 0; nn < 2; ++nn) {
        unsigned lk[4][2];
        #pragma unroll
        for (int k = 0; k < 4; ++k) {
            lk[k][0] = maxf2(c[nn][k][0], mulf2(c[nn][k][0], C02));
            lk[k][1] = maxf2(c[nn][k][1], mulf2(c[nn][k][1], C02));
        }
        int col0 = jc0 + 8 * nn + 2 * t4;
        #pragma unroll
        for (int hf = 0; hf < 2; ++hf) {
            int row = r0 + g + 8 * hf;
            float vD[2];
            #pragma unroll
            for (int e = 0; e < 2; ++e) {
                int t = (dirt[nn][hf] >> (8 * e)) & 0xff;
                unsigned sv = (t == 1) ? lk[0][hf] : (t == 2) ? lk[1][hf] :
                              (t == 3) ? lk[2][hf] : lk[3][hf];
                float v = half_ex(sv, e);
                vD[e] = (row < L_ && (col0 + e) < L_ && t) ? v : NEG_INF_;
            }
            if (row < 104 && col0 < 104)
                *(float2*)(al_sm + row * AS + col0) = make_float2(vD[0], vD[1]);
            if (do_mirror && row < L_) {
                #pragma unroll
                for (int e = 0; e < 2; ++e) {
                    int col = col0 + e;
                    if (col < L_) {
                        int tm = mirt[nn][hf][e];
                        unsigned sv = (tm == 1) ? lk[0][hf] : (tm == 2) ? lk[1][hf] :
                                      (tm == 3) ? lk[2][hf] : lk[3][hf];
                        float v = half_ex(sv, e);
                        al_sm[col * AS + row] = tm ? v : NEG_INF_;
                    }
                }
            }
        }
    }
}

__global__ __launch_bounds__(NT, 2)
void combine_graph_kernel(const int* __restrict__ inputs,
                          const int* __restrict__ adj,
                          const float* __restrict__ emb,
                          const float* __restrict__ a0p,
                          const float* __restrict__ a1p,
                          const float* __restrict__ a2p,
                          const float* __restrict__ a3p,
                          float* __restrict__ out)
{
    extern __shared__ char smem[];
    unsigned* hf_sm  = (unsigned*)(smem + OFF_HF);
    unsigned* atp_sm = (unsigned*)(smem + OFF_ATP);
    char*     adj_sm = smem + OFF_ADJ;
    float*    al_sm  = (float*)(smem + OFF_AL);
    unsigned* al32   = (unsigned*)(smem + OFF_AL);
    const uint32_t hf_u = smem_u32(smem + OFF_HF);
    const uint32_t al_u = smem_u32(smem + OFF_AL);

    const int b    = blockIdx.x;
    const int tid  = threadIdx.x;
    const int w    = tid >> 5;
    const int lane = tid & 31;
    const int g    = lane >> 2;
    const int t4   = lane & 3;

    const int* inp  = inputs + b * L_;
    const int* adjb = adj + (size_t)b * (L_ * L_);

    // ---------------- phase 0: loads ----------------
    if (tid < 256) {   // atp[wd] = {pack(a0),pack(a1),pack(a2),pack(a3)} for word wd
        int wd = tid & 63, k = tid >> 6;
        const float* ap = (k == 0) ? a0p : (k == 1) ? a1p : (k == 2) ? a2p : a3p;
        ((unsigned*)((uint4*)atp_sm + wd))[k] = pack_f16x2(ap[2 * wd], ap[2 * wd + 1]);
    }
    // embedding gather -> h fp16; rows 100..103 zero (unrolled for LDG batching)
    #pragma unroll
    for (int it = 0; it < 7; ++it) {
        int e = tid + it * NT;
        if (e < 104 * 32) {
            int r = e >> 5, q = e & 31;
            float4 v = make_float4(0.f, 0.f, 0.f, 0.f);
            if (r < L_) {
                int id = inp[r];
                v = ((const float4*)(emb + (size_t)id * D_))[q];
            }
            *(uint2*)(hf_sm + r * HB + 2 * q) = make_uint2(pack_f16x2(v.x, v.y),
                                                           pack_f16x2(v.z, v.w));
        }
    }
    // adj -> int8 (unrolled for LDG batching)
    #pragma unroll
    for (int it = 0; it < 5; ++it) {
        int e = tid + it * NT;
        if (e < 2500) {
            int i = e / 25, c = e % 25;
            int4 v = ((const int4*)(adjb + i * 100))[c];
            unsigned p = (unsigned)(v.x & 0xff) | ((unsigned)(v.y & 0xff) << 8)
                       | ((unsigned)(v.z & 0xff) << 16) | ((unsigned)(v.w & 0xff) << 24);
            *(unsigned*)(adj_sm + i * ADJS + c * 4) = p;
        }
    }
    __syncthreads();

    // ---- GEMM1: 28 upper-triangle m16n16 tiles over 16 warps (rounds 16 + 12) ----
    {
        int mt, np;
        decode_job(w, mt, np);
        gemm1_job(smem, mt, np, hf_u, lane, g, t4);
        if (w + 16 < 28) {
            decode_job(w + 16, mt, np);
            gemm1_job(smem, mt, np, hf_u, lane, g, t4);
        }
    }
    __syncthreads();

    // -------- softmax: al f32 row -> fp16 alpha in words 0..51 (in place) --------
    for (int i = w; i < L_; i += 16) {
        float4 x = make_float4(NEG_INF_, NEG_INF_, NEG_INF_, NEG_INF_);
        if (lane < 26) x = *(const float4*)(al_sm + i * AS + 4 * lane);
        float mx = fmaxf(fmaxf(x.x, x.y), fmaxf(x.z, x.w));
        #pragma unroll
        for (int o = 16; o > 0; o >>= 1) mx = fmaxf(mx, __shfl_xor_sync(0xffffffffu, mx, o));
        float4 ev = make_float4(0.f, 0.f, 0.f, 0.f);
        if (lane < 25) {   // cols 100..103 masked out
            ev.x = __expf(x.x - mx); ev.y = __expf(x.y - mx);
            ev.z = __expf(x.z - mx); ev.w = __expf(x.w - mx);
        }
        float s = (ev.x + ev.y) + (ev.z + ev.w);
        #pragma unroll
        for (int o = 16; o > 0; o >>= 1) s += __shfl_xor_sync(0xffffffffu, s, o);
        float inv = 1.f / s;
        if (lane < 26) {   // warp-synchronous: all reads done before these writes
            float a0 = ev.x * inv, a1 = ev.y * inv, a2 = ev.z * inv, a3 = ev.w * inv;
            *(uint2*)(al32 + i * AS + 2 * lane) = make_uint2(pack_f16x2(a0, a1),
                                                             pack_f16x2(a2, a3));
        }
    }
    // zero fp16-alpha rows 100..103 (GEMM2 A-fragment clamp reads row 103)
    if (tid < 208) {
        int rr = tid / 52, cc = tid % 52;
        al32[(100 + rr) * AS + cc] = 0u;
    }
    __syncthreads();

    // ---------- GEMM2: out = alpha @ h (fp16, ldmatrix, rounds 16 + 12) ----------
    #pragma unroll
    for (int kk = 0; kk < 2; ++kk) {
        int job = w + 16 * kk;
        if (job < 28) {
            int mt16 = job >> 2;          // 0..6
            int nq   = job & 3;           // n32 quarter of D
            const int r0 = mt16 * 16;

            int rowA = r0 + (lane & 15); if (rowA > 103) rowA = 103;
            uint32_t ahA  = al_u + (uint32_t)(rowA * (AS * 4)) + (uint32_t)((lane >> 4) << 4);
            uint32_t ahA6 = al_u + (uint32_t)(rowA * (AS * 4)) + 192u;
            const uint32_t bcol = (uint32_t)(nq * 64) + (uint32_t)((lane >> 4) << 4);

            float c[4][4];
            #pragma unroll
            for (int n = 0; n < 4; ++n)
                #pragma unroll
                for (int p = 0; p < 4; ++p) c[n][p] = 0.f;

            #pragma unroll 1
            for (int kt = 0; kt < 7; ++kt) {
                int jr = kt * 16 + (lane & 15); if (jr > 103) jr = 103;
                uint32_t boff = (uint32_t)(jr * (HB * 4)) + bcol;
                unsigned hh[8];
                ldsm_x4t(hh[0], hh[1], hh[2], hh[3], hf_u + boff);
                ldsm_x4t(hh[4], hh[5], hh[6], hh[7], hf_u + boff + 32u);
                unsigned A[4];
                if (kt < 6) {
                    ldsm_x4(A[0], A[1], A[2], A[3], ahA + kt * 32u);
                } else {
                    ldsm_x2(A[0], A[1], ahA6); A[2] = 0u; A[3] = 0u;
                }
                #pragma unroll
                for (int n = 0; n < 4; ++n)
                    mma_f16(c[n], A[0], A[1], A[2], A[3], hh[2 * n], hh[2 * n + 1]);
            }
            float* outb = out + (size_t)b * (L_ * D_);
            #pragma unroll
            for (int n = 0; n < 4; ++n) {
                #pragma unroll
                for (int p = 0; p < 2; ++p) {
                    int row = r0 + g + p * 8;
                    if (row < L_) {
                        int colo = nq * 32 + n * 8 + t4 * 2;
                        float2 v2 = make_float2(c[n][p * 2], c[n][p * 2 + 1]);
                        *(float2*)(outb + row * D_ + colo) = v2;
                    }
                }
            }
        }
    }
}

extern "C" void kernel_launch(void* const* d_in, const int* in_sizes, int n_in,
                              void* d_out, int out_size) {
    // metadata order: inputs, adj, mask_item, item, emb_table, a0, a1, a2, a3
    const int*   inputs = (const int*)d_in[0];
    const int*   adj    = (const int*)d_in[1];
    const float* emb    = (const float*)d_in[4];
    const float* a0     = (const float*)d_in[5];
    const float* a1     = (const float*)d_in[6];
    const float* a2     = (const float*)d_in[7];
    const float* a3     = (const float*)d_in[8];
    float* out = (float*)d_out;

    cudaFuncSetAttribute(combine_graph_kernel,
                         cudaFuncAttributeMaxDynamicSharedMemorySize, SMEM_TOTAL);

    combine_graph_kernel<<<B_, NT, SMEM_TOTAL>>>(inputs, adj, emb, a0, a1, a2, a3, out);
}